// round 2
// baseline (speedup 1.0000x reference)
#include <cuda_runtime.h>

#define W_IMG   160
#define H_IMG   160
#define NBITS   128
#define TILE_W  168          // padded row stride in words (166 used)
#define TILE_COLS 166
#define R_ROWS  8            // output rows per thread
#define TILE_ROWS (R_ROWS + 5)   // 13: y1 in [0,5], +1 for bilinear
#define PADIMG  3

// grid: 32 (n) * 20 (row-groups of 8) * 2 (bit halves) = 1280 blocks, 160 threads
__global__ __launch_bounds__(160, 6)
void fern_kernel(const float* __restrict__ x,
                 const float* __restrict__ dx1, const float* __restrict__ dx2,
                 const float* __restrict__ dy1, const float* __restrict__ dy2,
                 const float* __restrict__ th,
                 float* __restrict__ out)
{
    __shared__ float  tile[TILE_ROWS * TILE_W];
    __shared__ float4 swa[NBITS];
    __shared__ float4 swb[NBITS];
    __shared__ float  sc0[NBITS];
    __shared__ int    soffA[NBITS];
    __shared__ int    soffB[NBITS];
    __shared__ float  red[128];

    const int t   = threadIdx.x;        // 0..159
    const int bx  = blockIdx.x;         // 0..1279
    const int n   = bx / 40;
    const int rem = bx - n * 40;
    const int h0  = (rem >> 1) * R_ROWS;
    const int bit0 = (rem & 1) * (NBITS / 2);

    // ---- per-block param precompute (replicates reference int/float quirks) ----
    if (t < 128) {
        float a = fabsf(dx1[t]), b = fabsf(dx2[t]);
        float c = fabsf(dy1[t]), d = fabsf(dy2[t]);
        red[t] = fmaxf(fmaxf(a, b), fmaxf(c, d));
    }
    __syncthreads();
    #pragma unroll
    for (int s = 64; s > 0; s >>= 1) {
        if (t < s) red[t] = fmaxf(red[t], red[t + s]);
        __syncthreads();
    }
    const float L = red[0];

    if (t < 128) {
        int p = (int)ceilf(L);
        int shift = PADIMG - p;
        float dxa = dx1[t], dya = dy1[t];
        float dxb = dx2[t], dyb = dy2[t];
        float fla = floorf(dxa), flya = floorf(dya);
        float flb = floorf(dxb), flyb = floorf(dyb);
        float fxa = dxa - fla,  fya = dya - flya;
        float fxb = dxb - flb,  fyb = dyb - flyb;
        // int32 cast truncates toward zero, exactly like jnp astype(int32)
        int x1a = (int)(L + fla)  + shift;
        int y1a = (int)(L + flya) + shift;
        int x1b = (int)(L + flb)  + shift;
        int y1b = (int)(L + flyb) + shift;
        // jax.lax.dynamic_slice clamps start to [0, padded - slice] = [0, 5]
        x1a = min(max(x1a, 0), 5);  y1a = min(max(y1a, 0), 5);
        x1b = min(max(x1b, 0), 5);  y1b = min(max(y1b, 0), 5);

        float4 wa, wb;
        wa.x =  0.25f * (1.f - fxa) * (1.f - fya);
        wa.y =  0.25f * fxa         * (1.f - fya);
        wa.z =  0.25f * (1.f - fxa) * fya;
        wa.w =  0.25f * fxa         * fya;
        wb.x = -0.25f * (1.f - fxb) * (1.f - fyb);
        wb.y = -0.25f * fxb         * (1.f - fyb);
        wb.z = -0.25f * (1.f - fxb) * fyb;
        wb.w = -0.25f * fxb         * fyb;
        swa[t] = wa;  swb[t] = wb;
        sc0[t]   = 0.125f - 0.25f * th[t];
        soffA[t] = y1a * TILE_W + x1a;
        soffB[t] = y1b * TILE_W + x1b;
    }

    // ---- zero-padded input tile (channel 1 only) ----
    const float* ch = x + ((size_t)n * 3 + 1) * (size_t)(H_IMG * W_IMG);
    for (int i = t; i < TILE_ROWS * TILE_COLS; i += 160) {
        int rr = i / TILE_COLS;
        int cc = i - rr * TILE_COLS;
        int gr = h0 + rr - PADIMG;
        int gc = cc - PADIMG;
        float v = 0.f;
        if ((unsigned)gr < (unsigned)H_IMG && (unsigned)gc < (unsigned)W_IMG)
            v = __ldg(ch + gr * W_IMG + gc);
        tile[rr * TILE_W + cc] = v;
    }
    __syncthreads();

    const int w = t;   // lanes are consecutive w -> conflict-free LDS, coalesced STG
    float* o = out + ((size_t)n * NBITS + bit0) * (size_t)(H_IMG * W_IMG)
                   + (size_t)h0 * W_IMG + w;

    #pragma unroll 1
    for (int bi = 0; bi < NBITS / 2; bi++) {
        const int b = bit0 + bi;
        const float4 wa = swa[b];
        const float4 wb = swb[b];
        const float  c0 = sc0[b];
        const float* pa = tile + soffA[b] + w;
        const float* pb = tile + soffB[b] + w;

        float acc[R_ROWS];
        float a0 = pa[0], a1 = pa[1];
        #pragma unroll
        for (int r = 0; r < R_ROWS; r++) {
            float b0 = pa[(r + 1) * TILE_W];
            float b1 = pa[(r + 1) * TILE_W + 1];
            float v = fmaf(wa.x, a0, c0);
            v = fmaf(wa.y, a1, v);
            v = fmaf(wa.z, b0, v);
            acc[r] = fmaf(wa.w, b1, v);
            a0 = b0; a1 = b1;
        }
        a0 = pb[0]; a1 = pb[1];
        #pragma unroll
        for (int r = 0; r < R_ROWS; r++) {
            float b0 = pb[(r + 1) * TILE_W];
            float b1 = pb[(r + 1) * TILE_W + 1];
            float v = fmaf(wb.x, a0, acc[r]);
            v = fmaf(wb.y, a1, v);
            v = fmaf(wb.z, b0, v);
            acc[r] = fmaf(wb.w, b1, v);
            a0 = b0; a1 = b1;
        }
        #pragma unroll
        for (int r = 0; r < R_ROWS; r++)
            o[(size_t)r * W_IMG] = __saturatef(acc[r]);

        o += (size_t)H_IMG * W_IMG;
    }
}

extern "C" void kernel_launch(void* const* d_in, const int* in_sizes, int n_in,
                              void* d_out, int out_size)
{
    const float* x   = (const float*)d_in[0];
    const float* dx1 = (const float*)d_in[1];
    const float* dx2 = (const float*)d_in[2];
    const float* dy1 = (const float*)d_in[3];
    const float* dy2 = (const float*)d_in[4];
    const float* th  = (const float*)d_in[5];
    float* out = (float*)d_out;

    dim3 grid(32 * 20 * 2);
    dim3 block(160);
    fern_kernel<<<grid, block>>>(x, dx1, dx2, dy1, dy2, th, out);
}